// round 1
// baseline (speedup 1.0000x reference)
#include <cuda_runtime.h>
#include <cuda_bf16.h>
#include <math.h>

// ---------------- problem constants ----------------
#define T_LEN   4096
#define R_LEN   49
#define D_LEN   512
#define N_SEG   256
#define N_CLASS 106
#define N_CAT   18

// output layout: keysteps[106*256], cats[18], alphas_sp[4096*49], alphas_ks[106]
#define OUT_KS   0
#define OUT_CATS (N_CLASS * N_SEG)
#define OUT_ASP  (OUT_CATS + N_CAT)
#define OUT_AKS  (OUT_ASP + T_LEN * R_LEN)

// ---------------- scratch ----------------
__device__ float g_segsum[N_SEG * D_LEN];
__device__ float g_cnt[N_SEG];
__device__ float g_x[D_LEN * N_SEG];          // fbar_seg transposed: [d][s]
__device__ float g_w1t[3 * D_LEN * D_LEN];    // w1 transposed: [k][i][o]
__device__ float g_h[D_LEN * N_SEG];          // conv1 output (relu): [o][s]
__device__ float g_att[N_CLASS * N_SEG];      // softmax over classes: [m][s]
__device__ float g_fk[N_CLASS * D_LEN];       // f_keysteps: [m][d]

// ---------------- K0: zero segment accumulators ----------------
__global__ void k_zero() {
    int i = blockIdx.x * 256 + threadIdx.x;
    if (i < N_SEG * D_LEN) g_segsum[i] = 0.f;
    if (i < N_SEG) g_cnt[i] = 0.f;
}

// ---------------- K_wt: transpose conv1 weights [O,I,K] -> [K,I,O] ----------------
__global__ void k_wt(const float* __restrict__ w1) {
    int i = blockIdx.x * 256 + threadIdx.x;
    if (i < D_LEN * D_LEN * 3) {
        int o = i / (D_LEN * 3);
        int rem = i - o * (D_LEN * 3);
        int ii = rem / 3;
        int k = rem - ii * 3;
        g_w1t[(k * D_LEN + ii) * D_LEN + o] = w1[i];
    }
}

// ---------------- K1: spatial attention + segment accumulation ----------------
// one block per t; 512 threads; feature slice staged in dynamic smem (100KB)
__global__ void k_spatial(const float* __restrict__ feature,
                          const int* __restrict__ seg_ids,
                          const float* __restrict__ att_w,
                          const float* __restrict__ att_b,
                          float* __restrict__ alphas_out) {
    extern __shared__ float smem[];
    float* f  = smem;                       // 49*512
    float* w  = smem + R_LEN * D_LEN;       // 512
    float* sv = w + D_LEN;                  // 64

    const int t = blockIdx.x;
    const int tid = threadIdx.x;
    const int warp = tid >> 5, lane = tid & 31;

    w[tid] = att_w[tid];

    // load feature[t] via float4 (49*512 floats = 6272 float4)
    const float4* src = (const float4*)(feature + (size_t)t * (R_LEN * D_LEN));
    float4* dst = (float4*)f;
    #pragma unroll 4
    for (int i = tid; i < R_LEN * (D_LEN / 4); i += 512) dst[i] = src[i];
    __syncthreads();

    // per-row dot: 16 warps, rows strided by 16
    for (int r = warp; r < R_LEN; r += 16) {
        float acc = 0.f;
        const float* fr = f + r * D_LEN;
        #pragma unroll 4
        for (int d = lane; d < D_LEN; d += 32) acc += fr[d] * w[d];
        #pragma unroll
        for (int o = 16; o; o >>= 1) acc += __shfl_xor_sync(0xffffffffu, acc, o);
        if (!lane) sv[r] = acc + att_b[0];
    }
    __syncthreads();

    // softmax over 49 rows (warp 0)
    if (warp == 0) {
        float v0 = (lane < R_LEN) ? sv[lane] : -1e30f;
        float v1 = (lane + 32 < R_LEN) ? sv[lane + 32] : -1e30f;
        float mx = fmaxf(v0, v1);
        #pragma unroll
        for (int o = 16; o; o >>= 1) mx = fmaxf(mx, __shfl_xor_sync(0xffffffffu, mx, o));
        float e0 = (lane < R_LEN) ? __expf(v0 - mx) : 0.f;
        float e1 = (lane + 32 < R_LEN) ? __expf(v1 - mx) : 0.f;
        float sum = e0 + e1;
        #pragma unroll
        for (int o = 16; o; o >>= 1) sum += __shfl_xor_sync(0xffffffffu, sum, o);
        float inv = 1.f / sum;
        if (lane < R_LEN) {
            float a = e0 * inv;
            sv[lane] = a;
            alphas_out[t * R_LEN + lane] = a;
        }
        if (lane + 32 < R_LEN) {
            float a = e1 * inv;
            sv[lane + 32] = a;
            alphas_out[t * R_LEN + lane + 32] = a;
        }
    }
    __syncthreads();

    // fbar[d] = sum_r f[r][d] * alpha[r], accumulate into segment sum
    float acc = 0.f;
    #pragma unroll
    for (int r = 0; r < R_LEN; r++) acc += f[r * D_LEN + tid] * sv[r];
    int seg = seg_ids[t];
    atomicAdd(&g_segsum[seg * D_LEN + tid], acc);
    if (tid == 0) atomicAdd(&g_cnt[seg], 1.f);
}

// ---------------- K2: segment mean -> x[d][s] ----------------
__global__ void k_segmean() {
    int s = blockIdx.x;
    int d = threadIdx.x;
    float c = fmaxf(g_cnt[s], 1.f);
    g_x[d * N_SEG + s] = g_segsum[s * D_LEN + d] / c;
}

// ---------------- K3: conv1 (k=3, SAME) as tiled GEMM + relu ----------------
// grid (16, 8): o-tiles x s-tiles of 32x32; 256 threads; 2x2 per thread
__global__ void k_conv1(const float* __restrict__ b1) {
    __shared__ float Wt[32][33];  // [ii][oo]
    __shared__ float Xt[32][33];  // [ii][ss]
    int o0 = blockIdx.x * 32, s0 = blockIdx.y * 32;
    int tid = threadIdx.x;
    int tx = tid & 15, ty = tid >> 4;
    float acc00 = 0.f, acc01 = 0.f, acc10 = 0.f, acc11 = 0.f;

    for (int k = 0; k < 3; k++) {
        for (int ic = 0; ic < D_LEN; ic += 32) {
            #pragma unroll
            for (int l = tid; l < 1024; l += 256) {
                int ii = l >> 5, oo = l & 31;
                Wt[ii][oo] = g_w1t[(k * D_LEN + ic + ii) * D_LEN + o0 + oo];
            }
            #pragma unroll
            for (int l = tid; l < 1024; l += 256) {
                int ii = l >> 5, ss = l & 31;
                int sc = s0 + ss + k - 1;
                Xt[ii][ss] = (sc >= 0 && sc < N_SEG) ? g_x[(ic + ii) * N_SEG + sc] : 0.f;
            }
            __syncthreads();
            #pragma unroll
            for (int ii = 0; ii < 32; ii++) {
                float w0 = Wt[ii][ty], w1v = Wt[ii][ty + 16];
                float x0 = Xt[ii][tx], x1v = Xt[ii][tx + 16];
                acc00 += w0 * x0; acc01 += w0 * x1v;
                acc10 += w1v * x0; acc11 += w1v * x1v;
            }
            __syncthreads();
        }
    }
    float bia0 = b1[o0 + ty], bia1 = b1[o0 + ty + 16];
    g_h[(o0 + ty)      * N_SEG + s0 + tx]      = fmaxf(acc00 + bia0, 0.f);
    g_h[(o0 + ty)      * N_SEG + s0 + tx + 16] = fmaxf(acc01 + bia0, 0.f);
    g_h[(o0 + ty + 16) * N_SEG + s0 + tx]      = fmaxf(acc10 + bia1, 0.f);
    g_h[(o0 + ty + 16) * N_SEG + s0 + tx + 16] = fmaxf(acc11 + bia1, 0.f);
}

// ---------------- K4: conv2 (1x1) + softmax over classes, fused ----------------
// 32 blocks, each handles 8 consecutive s columns; 256 threads = 8 warps
__global__ void k_conv2(const float* __restrict__ w2,
                        const float* __restrict__ b2,
                        float* __restrict__ out_ks) {
    __shared__ float hc[D_LEN * 9];      // [i][j], pad 9
    __shared__ float lg[112 * 9];        // logits [m][j], pad 9
    int s0 = blockIdx.x * 8;
    int tid = threadIdx.x;
    int warp = tid >> 5, lane = tid & 31;

    for (int l = tid; l < D_LEN * 8; l += 256) {
        int i = l >> 3, j = l & 7;
        hc[i * 9 + j] = g_h[i * N_SEG + s0 + j];
    }
    __syncthreads();

    for (int m = warp; m < N_CLASS; m += 8) {
        float acc[8] = {0.f, 0.f, 0.f, 0.f, 0.f, 0.f, 0.f, 0.f};
        const float* wm = w2 + m * D_LEN;
        for (int i = lane; i < D_LEN; i += 32) {
            float wv = wm[i];
            const float* hp = &hc[i * 9];
            #pragma unroll
            for (int j = 0; j < 8; j++) acc[j] += wv * hp[j];
        }
        #pragma unroll
        for (int j = 0; j < 8; j++) {
            float a = acc[j];
            #pragma unroll
            for (int o = 16; o; o >>= 1) a += __shfl_xor_sync(0xffffffffu, a, o);
            acc[j] = a;
        }
        if (!lane) {
            float bb = b2[m];
            #pragma unroll
            for (int j = 0; j < 8; j++) lg[m * 9 + j] = acc[j] + bb;
        }
    }
    __syncthreads();

    // softmax over m for s = s0 + warp (8 warps -> 8 columns)
    {
        int j = warp;
        int s = s0 + j;
        float v[4], mx = -1e30f;
        #pragma unroll
        for (int q = 0; q < 4; q++) {
            int m = lane + 32 * q;
            v[q] = (m < N_CLASS) ? lg[m * 9 + j] : -1e30f;
            mx = fmaxf(mx, v[q]);
        }
        #pragma unroll
        for (int o = 16; o; o >>= 1) mx = fmaxf(mx, __shfl_xor_sync(0xffffffffu, mx, o));
        float e[4], sum = 0.f;
        #pragma unroll
        for (int q = 0; q < 4; q++) {
            int m = lane + 32 * q;
            e[q] = (m < N_CLASS) ? __expf(v[q] - mx) : 0.f;
            sum += e[q];
        }
        #pragma unroll
        for (int o = 16; o; o >>= 1) sum += __shfl_xor_sync(0xffffffffu, sum, o);
        float inv = 1.f / sum;
        #pragma unroll
        for (int q = 0; q < 4; q++) {
            int m = lane + 32 * q;
            if (m < N_CLASS) {
                out_ks[m * N_SEG + s] = v[q];
                g_att[m * N_SEG + s] = e[q] * inv;
            }
        }
    }
}

// ---------------- K5: f_keysteps[m][d] = sum_s x[d][s] * att[m][s] ----------------
// 27 blocks of 4 m-rows; 512 threads = d
__global__ void k_fk() {
    __shared__ float a[4][N_SEG];
    int m0 = blockIdx.x * 4;
    int tid = threadIdx.x;
    for (int l = tid; l < 4 * N_SEG; l += 512) {
        int mm = l >> 8, s = l & 255;
        int m = m0 + mm;
        a[mm][s] = (m < N_CLASS) ? g_att[m * N_SEG + s] : 0.f;
    }
    __syncthreads();
    int d = tid;
    const float* xr = g_x + d * N_SEG;
    float a0 = 0.f, a1 = 0.f, a2 = 0.f, a3 = 0.f;
    #pragma unroll 4
    for (int s = 0; s < N_SEG; s++) {
        float xv = xr[s];
        a0 += xv * a[0][s];
        a1 += xv * a[1][s];
        a2 += xv * a[2][s];
        a3 += xv * a[3][s];
    }
    if (m0 + 0 < N_CLASS) g_fk[(m0 + 0) * D_LEN + d] = a0;
    if (m0 + 1 < N_CLASS) g_fk[(m0 + 1) * D_LEN + d] = a1;
    if (m0 + 2 < N_CLASS) g_fk[(m0 + 2) * D_LEN + d] = a2;
    if (m0 + 3 < N_CLASS) g_fk[(m0 + 3) * D_LEN + d] = a3;
}

// ---------------- K6: keystep attention + categories ----------------
// single block, 512 threads
__global__ void k_final(const float* __restrict__ att2_w,
                        const float* __restrict__ att2_b,
                        const float* __restrict__ cls_w,
                        const float* __restrict__ cls_b,
                        float* __restrict__ out_aks,
                        float* __restrict__ out_cats) {
    __shared__ float s2[128];
    __shared__ float alpha[128];
    __shared__ float fv[D_LEN];
    int tid = threadIdx.x;
    int warp = tid >> 5, lane = tid & 31;

    for (int m = warp; m < N_CLASS; m += 16) {
        float acc = 0.f;
        const float* fm = g_fk + m * D_LEN;
        for (int d = lane; d < D_LEN; d += 32) acc += fm[d] * att2_w[d];
        #pragma unroll
        for (int o = 16; o; o >>= 1) acc += __shfl_xor_sync(0xffffffffu, acc, o);
        if (!lane) s2[m] = acc + att2_b[0];
    }
    __syncthreads();

    if (warp == 0) {
        float v[4], mx = -1e30f;
        #pragma unroll
        for (int q = 0; q < 4; q++) {
            int m = lane + 32 * q;
            v[q] = (m < N_CLASS) ? s2[m] : -1e30f;
            mx = fmaxf(mx, v[q]);
        }
        #pragma unroll
        for (int o = 16; o; o >>= 1) mx = fmaxf(mx, __shfl_xor_sync(0xffffffffu, mx, o));
        float e[4], sum = 0.f;
        #pragma unroll
        for (int q = 0; q < 4; q++) {
            int m = lane + 32 * q;
            e[q] = (m < N_CLASS) ? __expf(v[q] - mx) : 0.f;
            sum += e[q];
        }
        #pragma unroll
        for (int o = 16; o; o >>= 1) sum += __shfl_xor_sync(0xffffffffu, sum, o);
        float inv = 1.f / sum;
        #pragma unroll
        for (int q = 0; q < 4; q++) {
            int m = lane + 32 * q;
            if (m < N_CLASS) {
                float a = e[q] * inv;
                alpha[m] = a;
                out_aks[m] = a;
            }
        }
    }
    __syncthreads();

    {
        int d = tid;
        float acc = 0.f;
        for (int m = 0; m < N_CLASS; m++) acc += g_fk[m * D_LEN + d] * alpha[m];
        fv[d] = acc;
    }
    __syncthreads();

    for (int c = warp; c < N_CAT; c += 16) {
        float acc = 0.f;
        for (int d = lane; d < D_LEN; d += 32) acc += fv[d] * cls_w[d * N_CAT + c];
        #pragma unroll
        for (int o = 16; o; o >>= 1) acc += __shfl_xor_sync(0xffffffffu, acc, o);
        if (!lane) out_cats[c] = acc + cls_b[c];
    }
}

// ---------------- launch ----------------
extern "C" void kernel_launch(void* const* d_in, const int* in_sizes, int n_in,
                              void* d_out, int out_size) {
    const float* feature = (const float*)d_in[0];
    const int*   seg_ids = (const int*)d_in[1];
    const float* att_w   = (const float*)d_in[2];
    const float* att_b   = (const float*)d_in[3];
    const float* att2_w  = (const float*)d_in[4];
    const float* att2_b  = (const float*)d_in[5];
    const float* fcsn_w1 = (const float*)d_in[6];
    const float* fcsn_b1 = (const float*)d_in[7];
    const float* fcsn_w2 = (const float*)d_in[8];
    const float* fcsn_b2 = (const float*)d_in[9];
    const float* cls_w   = (const float*)d_in[10];
    const float* cls_b   = (const float*)d_in[11];

    float* out = (float*)d_out;
    float* out_ks   = out + OUT_KS;
    float* out_cats = out + OUT_CATS;
    float* out_asp  = out + OUT_ASP;
    float* out_aks  = out + OUT_AKS;

    // K1 dynamic smem: (49*512 + 512 + 64) floats
    const int smem1 = (R_LEN * D_LEN + D_LEN + 64) * sizeof(float);
    cudaFuncSetAttribute(k_spatial, cudaFuncAttributeMaxDynamicSharedMemorySize, smem1);

    k_zero<<<(N_SEG * D_LEN + 255) / 256, 256>>>();
    k_wt<<<(D_LEN * D_LEN * 3 + 255) / 256, 256>>>(fcsn_w1);
    k_spatial<<<T_LEN, 512, smem1>>>(feature, seg_ids, att_w, att_b, out_asp);
    k_segmean<<<N_SEG, D_LEN>>>();
    {
        dim3 g(D_LEN / 32, N_SEG / 32);
        k_conv1<<<g, 256>>>(fcsn_b1);
    }
    k_conv2<<<N_SEG / 8, 256>>>(fcsn_w2, fcsn_b2, out_ks);
    k_fk<<<(N_CLASS + 3) / 4, 512>>>();
    k_final<<<1, 512>>>(att2_w, att2_b, cls_w, cls_b, out_aks, out_cats);
}

// round 2
// speedup vs baseline: 1.1546x; 1.1546x over previous
#include <cuda_runtime.h>
#include <cuda_bf16.h>
#include <cstdint>
#include <math.h>

// ---------------- problem constants ----------------
#define T_LEN   4096
#define R_LEN   49
#define D_LEN   512
#define N_SEG   256
#define N_CLASS 106
#define N_CAT   18

#define FEAT_FLOATS (R_LEN * D_LEN)       // 25088
#define FEAT_BYTES  (FEAT_FLOATS * 4)     // 100352

// output layout: keysteps[106*256], cats[18], alphas_sp[4096*49], alphas_ks[106]
#define OUT_KS   0
#define OUT_CATS (N_CLASS * N_SEG)
#define OUT_ASP  (OUT_CATS + N_CAT)
#define OUT_AKS  (OUT_ASP + T_LEN * R_LEN)

// ---------------- scratch ----------------
__device__ float g_segsum[N_SEG * D_LEN];
__device__ float g_cnt[N_SEG];
__device__ float g_x[D_LEN * N_SEG];          // fbar_seg transposed: [d][s]
__device__ float g_w1t[3 * D_LEN * D_LEN];    // w1 transposed: [k][i][o]
__device__ float g_h[D_LEN * N_SEG];          // conv1 output (relu): [o][s]
__device__ float g_att[N_CLASS * N_SEG];      // softmax over classes: [m][s]
__device__ float g_fk[N_CLASS * D_LEN];       // f_keysteps: [m][d]

// ---------------- PTX helpers ----------------
__device__ __forceinline__ uint32_t smem_u32(const void* p) {
    return (uint32_t)__cvta_generic_to_shared(p);
}

#define MBAR_INIT(addr, cnt) \
    asm volatile("mbarrier.init.shared.b64 [%0], %1;" :: "r"(addr), "r"(cnt) : "memory")

#define MBAR_EXPECT_TX(addr, bytes) \
    asm volatile("mbarrier.arrive.expect_tx.shared.b64 _, [%0], %1;" :: "r"(addr), "r"(bytes) : "memory")

#define BULK_G2S(dst_u32, src_ptr, bytes, mbar_u32) \
    asm volatile("cp.async.bulk.shared::cta.global.mbarrier::complete_tx::bytes [%0], [%1], %2, [%3];" \
        :: "r"(dst_u32), "l"(src_ptr), "r"(bytes), "r"(mbar_u32) : "memory")

#define MBAR_WAIT_PARITY(addr, parity) do {                                       \
    uint32_t _done = 0;                                                           \
    while (!_done) {                                                              \
        asm volatile("{\n\t.reg .pred p;\n\t"                                     \
                     "mbarrier.try_wait.parity.shared.b64 p, [%1], %2;\n\t"       \
                     "selp.b32 %0, 1, 0, p;\n\t}"                                 \
                     : "=r"(_done) : "r"(addr), "r"(parity) : "memory");          \
    }                                                                             \
} while (0)

// ---------------- K0: zero segment accumulators ----------------
__global__ void k_zero() {
    int i = blockIdx.x * 256 + threadIdx.x;
    if (i < N_SEG * D_LEN) g_segsum[i] = 0.f;
    if (i < N_SEG) g_cnt[i] = 0.f;
}

// ---------------- K_wt: tiled transpose conv1 weights [O,I,K] -> [K,I,O] ----------------
// grid (16 o-tiles, 16 i-tiles, 3 k); block (32, 8)
__global__ void k_wt(const float* __restrict__ w1) {
    __shared__ float tl[32][33];
    int o0 = blockIdx.x * 32, i0 = blockIdx.y * 32, k = blockIdx.z;
    int tx = threadIdx.x, ty = threadIdx.y;
    #pragma unroll
    for (int j = ty; j < 32; j += 8)
        tl[j][tx] = w1[(size_t)(o0 + j) * (D_LEN * 3) + (i0 + tx) * 3 + k];
    __syncthreads();
    #pragma unroll
    for (int j = ty; j < 32; j += 8)
        g_w1t[((size_t)k * D_LEN + i0 + j) * D_LEN + o0 + tx] = tl[tx][j];
}

// ---------------- K1: spatial attention + segment accumulation ----------------
// persistent blocks; double-buffered cp.async.bulk prefetch; 512 threads
__global__ void __launch_bounds__(512, 1)
k_spatial(const float* __restrict__ feature,
          const int* __restrict__ seg_ids,
          const float* __restrict__ att_w,
          const float* __restrict__ att_b,
          float* __restrict__ alphas_out) {
    extern __shared__ float smem[];
    float* buf0 = smem;                         // 25088
    float* buf1 = smem + FEAT_FLOATS;           // 25088
    float* w    = smem + 2 * FEAT_FLOATS;       // 512
    float* sv   = w + D_LEN;                    // 64
    uint64_t* mbar = (uint64_t*)(sv + 64);      // 2 x 8B

    const int tid = threadIdx.x;
    const int warp = tid >> 5, lane = tid & 31;
    const uint32_t mb0 = smem_u32(&mbar[0]);
    const uint32_t mb1 = smem_u32(&mbar[1]);

    if (tid == 0) {
        MBAR_INIT(mb0, 1);
        MBAR_INIT(mb1, 1);
    }
    w[tid] = att_w[tid];
    __syncthreads();

    // att_w in registers: wreg[j] = w[lane + 32*j]
    float wreg[16];
    #pragma unroll
    for (int j = 0; j < 16; j++) wreg[j] = w[lane + 32 * j];
    const float ab = att_b[0];

    const int stride = gridDim.x;
    const int t0 = blockIdx.x;

    // prefetch first tile
    if (t0 < T_LEN && tid == 0) {
        MBAR_EXPECT_TX(mb0, FEAT_BYTES);
        BULK_G2S(smem_u32(buf0), feature + (size_t)t0 * FEAT_FLOATS, FEAT_BYTES, mb0);
    }

    int ph0 = 0, ph1 = 0;
    int it = 0;
    for (int t = t0; t < T_LEN; t += stride, ++it) {
        const int cur = it & 1;
        const uint32_t mb_cur = cur ? mb1 : mb0;
        const uint32_t mb_oth = cur ? mb0 : mb1;
        float* f  = cur ? buf1 : buf0;
        float* fo = cur ? buf0 : buf1;

        // wait for current buffer
        if (cur) { MBAR_WAIT_PARITY(mb_cur, ph1); ph1 ^= 1; }
        else     { MBAR_WAIT_PARITY(mb_cur, ph0); ph0 ^= 1; }

        // prefetch next tile into the other buffer (consumed at it-1, fenced by trailing sync)
        const int tn = t + stride;
        if (tn < T_LEN && tid == 0) {
            MBAR_EXPECT_TX(mb_oth, FEAT_BYTES);
            BULK_G2S(smem_u32(fo), feature + (size_t)tn * FEAT_FLOATS, FEAT_BYTES, mb_oth);
        }

        // ---- per-row dots: 16 warps, rows strided by 16 ----
        for (int r = warp; r < R_LEN; r += 16) {
            const float* fr = f + r * D_LEN;
            float acc = 0.f;
            #pragma unroll
            for (int j = 0; j < 16; j++) acc += fr[lane + 32 * j] * wreg[j];
            #pragma unroll
            for (int o = 16; o; o >>= 1) acc += __shfl_xor_sync(0xffffffffu, acc, o);
            if (!lane) sv[r] = acc + ab;
        }
        __syncthreads();

        // ---- softmax over 49 rows (warp 0) ----
        if (warp == 0) {
            float v0 = (lane < R_LEN) ? sv[lane] : -1e30f;
            float v1 = (lane + 32 < R_LEN) ? sv[lane + 32] : -1e30f;
            float mx = fmaxf(v0, v1);
            #pragma unroll
            for (int o = 16; o; o >>= 1) mx = fmaxf(mx, __shfl_xor_sync(0xffffffffu, mx, o));
            float e0 = (lane < R_LEN) ? __expf(v0 - mx) : 0.f;
            float e1 = (lane + 32 < R_LEN) ? __expf(v1 - mx) : 0.f;
            float sum = e0 + e1;
            #pragma unroll
            for (int o = 16; o; o >>= 1) sum += __shfl_xor_sync(0xffffffffu, sum, o);
            float inv = 1.f / sum;
            if (lane < R_LEN) {
                float a = e0 * inv;
                sv[lane] = a;
                alphas_out[t * R_LEN + lane] = a;
            }
            if (lane + 32 < R_LEN) {
                float a = e1 * inv;
                sv[lane + 32] = a;
                alphas_out[t * R_LEN + lane + 32] = a;
            }
        }
        __syncthreads();

        // ---- fbar[d] = sum_r f[r][d]*alpha[r]; accumulate into segment ----
        float acc = 0.f;
        #pragma unroll
        for (int r = 0; r < R_LEN; r++) acc += f[r * D_LEN + tid] * sv[r];
        const int seg = __ldg(&seg_ids[t]);
        atomicAdd(&g_segsum[seg * D_LEN + tid], acc);
        if (tid == 0) atomicAdd(&g_cnt[seg], 1.f);
        __syncthreads();   // buffer f reusable by the next prefetch
    }
}

// ---------------- K2: segment mean + transpose -> x[d][s] (tiled, coalesced) ----------------
// grid (8 s-tiles, 16 d-tiles); block (32, 8)
__global__ void k_segmean() {
    __shared__ float tile[32][33];
    int s0 = blockIdx.x * 32, d0 = blockIdx.y * 32;
    int tx = threadIdx.x, ty = threadIdx.y;
    #pragma unroll
    for (int j = ty; j < 32; j += 8)
        tile[j][tx] = g_segsum[(s0 + j) * D_LEN + d0 + tx];
    __syncthreads();
    float c = fmaxf(g_cnt[s0 + tx], 1.f);
    float inv = 1.f / c;
    #pragma unroll
    for (int j = ty; j < 32; j += 8)
        g_x[(d0 + j) * N_SEG + s0 + tx] = tile[tx][j] * inv;
}

// ---------------- K3: conv1 (k=3, SAME) as tiled GEMM + relu ----------------
__global__ void k_conv1(const float* __restrict__ b1) {
    __shared__ float Wt[32][33];  // [ii][oo]
    __shared__ float Xt[32][33];  // [ii][ss]
    int o0 = blockIdx.x * 32, s0 = blockIdx.y * 32;
    int tid = threadIdx.x;
    int tx = tid & 15, ty = tid >> 4;
    float acc00 = 0.f, acc01 = 0.f, acc10 = 0.f, acc11 = 0.f;

    for (int k = 0; k < 3; k++) {
        for (int ic = 0; ic < D_LEN; ic += 32) {
            #pragma unroll
            for (int l = tid; l < 1024; l += 256) {
                int ii = l >> 5, oo = l & 31;
                Wt[ii][oo] = g_w1t[((size_t)k * D_LEN + ic + ii) * D_LEN + o0 + oo];
            }
            #pragma unroll
            for (int l = tid; l < 1024; l += 256) {
                int ii = l >> 5, ss = l & 31;
                int sc = s0 + ss + k - 1;
                Xt[ii][ss] = (sc >= 0 && sc < N_SEG) ? g_x[(ic + ii) * N_SEG + sc] : 0.f;
            }
            __syncthreads();
            #pragma unroll
            for (int ii = 0; ii < 32; ii++) {
                float w0 = Wt[ii][ty], w1v = Wt[ii][ty + 16];
                float x0 = Xt[ii][tx], x1v = Xt[ii][tx + 16];
                acc00 += w0 * x0; acc01 += w0 * x1v;
                acc10 += w1v * x0; acc11 += w1v * x1v;
            }
            __syncthreads();
        }
    }
    float bia0 = b1[o0 + ty], bia1 = b1[o0 + ty + 16];
    g_h[(o0 + ty)      * N_SEG + s0 + tx]      = fmaxf(acc00 + bia0, 0.f);
    g_h[(o0 + ty)      * N_SEG + s0 + tx + 16] = fmaxf(acc01 + bia0, 0.f);
    g_h[(o0 + ty + 16) * N_SEG + s0 + tx]      = fmaxf(acc10 + bia1, 0.f);
    g_h[(o0 + ty + 16) * N_SEG + s0 + tx + 16] = fmaxf(acc11 + bia1, 0.f);
}

// ---------------- K4: conv2 (1x1) + softmax over classes, fused ----------------
__global__ void k_conv2(const float* __restrict__ w2,
                        const float* __restrict__ b2,
                        float* __restrict__ out_ks) {
    __shared__ float hc[D_LEN * 9];      // [i][j], pad 9
    __shared__ float lg[112 * 9];        // logits [m][j], pad 9
    int s0 = blockIdx.x * 8;
    int tid = threadIdx.x;
    int warp = tid >> 5, lane = tid & 31;

    for (int l = tid; l < D_LEN * 8; l += 256) {
        int i = l >> 3, j = l & 7;
        hc[i * 9 + j] = g_h[i * N_SEG + s0 + j];
    }
    __syncthreads();

    for (int m = warp; m < N_CLASS; m += 8) {
        float acc[8] = {0.f, 0.f, 0.f, 0.f, 0.f, 0.f, 0.f, 0.f};
        const float* wm = w2 + m * D_LEN;
        #pragma unroll 4
        for (int i = lane; i < D_LEN; i += 32) {
            float wv = wm[i];
            const float* hp = &hc[i * 9];
            #pragma unroll
            for (int j = 0; j < 8; j++) acc[j] += wv * hp[j];
        }
        #pragma unroll
        for (int j = 0; j < 8; j++) {
            float a = acc[j];
            #pragma unroll
            for (int o = 16; o; o >>= 1) a += __shfl_xor_sync(0xffffffffu, a, o);
            acc[j] = a;
        }
        if (!lane) {
            float bb = b2[m];
            #pragma unroll
            for (int j = 0; j < 8; j++) lg[m * 9 + j] = acc[j] + bb;
        }
    }
    __syncthreads();

    // softmax over m for s = s0 + warp (8 warps -> 8 columns)
    {
        int j = warp;
        int s = s0 + j;
        float v[4], mx = -1e30f;
        #pragma unroll
        for (int q = 0; q < 4; q++) {
            int m = lane + 32 * q;
            v[q] = (m < N_CLASS) ? lg[m * 9 + j] : -1e30f;
            mx = fmaxf(mx, v[q]);
        }
        #pragma unroll
        for (int o = 16; o; o >>= 1) mx = fmaxf(mx, __shfl_xor_sync(0xffffffffu, mx, o));
        float e[4], sum = 0.f;
        #pragma unroll
        for (int q = 0; q < 4; q++) {
            int m = lane + 32 * q;
            e[q] = (m < N_CLASS) ? __expf(v[q] - mx) : 0.f;
            sum += e[q];
        }
        #pragma unroll
        for (int o = 16; o; o >>= 1) sum += __shfl_xor_sync(0xffffffffu, sum, o);
        float inv = 1.f / sum;
        #pragma unroll
        for (int q = 0; q < 4; q++) {
            int m = lane + 32 * q;
            if (m < N_CLASS) {
                out_ks[m * N_SEG + s] = v[q];
                g_att[m * N_SEG + s] = e[q] * inv;
            }
        }
    }
}

// ---------------- K5: f_keysteps[m][d] = sum_s x[d][s] * att[m][s] ----------------
__global__ void k_fk() {
    __shared__ float a[4][N_SEG];
    int m0 = blockIdx.x * 4;
    int tid = threadIdx.x;
    for (int l = tid; l < 4 * N_SEG; l += 512) {
        int mm = l >> 8, s = l & 255;
        int m = m0 + mm;
        a[mm][s] = (m < N_CLASS) ? g_att[m * N_SEG + s] : 0.f;
    }
    __syncthreads();
    int d = tid;
    const float* xr = g_x + d * N_SEG;
    float a0 = 0.f, a1 = 0.f, a2 = 0.f, a3 = 0.f;
    #pragma unroll 8
    for (int s = 0; s < N_SEG; s++) {
        float xv = xr[s];
        a0 += xv * a[0][s];
        a1 += xv * a[1][s];
        a2 += xv * a[2][s];
        a3 += xv * a[3][s];
    }
    if (m0 + 0 < N_CLASS) g_fk[(m0 + 0) * D_LEN + d] = a0;
    if (m0 + 1 < N_CLASS) g_fk[(m0 + 1) * D_LEN + d] = a1;
    if (m0 + 2 < N_CLASS) g_fk[(m0 + 2) * D_LEN + d] = a2;
    if (m0 + 3 < N_CLASS) g_fk[(m0 + 3) * D_LEN + d] = a3;
}

// ---------------- K6: keystep attention + categories ----------------
__global__ void k_final(const float* __restrict__ att2_w,
                        const float* __restrict__ att2_b,
                        const float* __restrict__ cls_w,
                        const float* __restrict__ cls_b,
                        float* __restrict__ out_aks,
                        float* __restrict__ out_cats) {
    __shared__ float s2[128];
    __shared__ float alpha[128];
    __shared__ float fv[D_LEN];
    int tid = threadIdx.x;
    int warp = tid >> 5, lane = tid & 31;

    for (int m = warp; m < N_CLASS; m += 16) {
        float acc = 0.f;
        const float* fm = g_fk + m * D_LEN;
        #pragma unroll 4
        for (int d = lane; d < D_LEN; d += 32) acc += fm[d] * att2_w[d];
        #pragma unroll
        for (int o = 16; o; o >>= 1) acc += __shfl_xor_sync(0xffffffffu, acc, o);
        if (!lane) s2[m] = acc + att2_b[0];
    }
    __syncthreads();

    if (warp == 0) {
        float v[4], mx = -1e30f;
        #pragma unroll
        for (int q = 0; q < 4; q++) {
            int m = lane + 32 * q;
            v[q] = (m < N_CLASS) ? s2[m] : -1e30f;
            mx = fmaxf(mx, v[q]);
        }
        #pragma unroll
        for (int o = 16; o; o >>= 1) mx = fmaxf(mx, __shfl_xor_sync(0xffffffffu, mx, o));
        float e[4], sum = 0.f;
        #pragma unroll
        for (int q = 0; q < 4; q++) {
            int m = lane + 32 * q;
            e[q] = (m < N_CLASS) ? __expf(v[q] - mx) : 0.f;
            sum += e[q];
        }
        #pragma unroll
        for (int o = 16; o; o >>= 1) sum += __shfl_xor_sync(0xffffffffu, sum, o);
        float inv = 1.f / sum;
        #pragma unroll
        for (int q = 0; q < 4; q++) {
            int m = lane + 32 * q;
            if (m < N_CLASS) {
                float a = e[q] * inv;
                alpha[m] = a;
                out_aks[m] = a;
            }
        }
    }
    __syncthreads();

    {
        int d = tid;
        float acc = 0.f;
        #pragma unroll 8
        for (int m = 0; m < N_CLASS; m++) acc += g_fk[m * D_LEN + d] * alpha[m];
        fv[d] = acc;
    }
    __syncthreads();

    for (int c = warp; c < N_CAT; c += 16) {
        float acc = 0.f;
        #pragma unroll 4
        for (int d = lane; d < D_LEN; d += 32) acc += fv[d] * cls_w[d * N_CAT + c];
        #pragma unroll
        for (int o = 16; o; o >>= 1) acc += __shfl_xor_sync(0xffffffffu, acc, o);
        if (!lane) out_cats[c] = acc + cls_b[c];
    }
}

// ---------------- launch ----------------
extern "C" void kernel_launch(void* const* d_in, const int* in_sizes, int n_in,
                              void* d_out, int out_size) {
    const float* feature = (const float*)d_in[0];
    const int*   seg_ids = (const int*)d_in[1];
    const float* att_w   = (const float*)d_in[2];
    const float* att_b   = (const float*)d_in[3];
    const float* att2_w  = (const float*)d_in[4];
    const float* att2_b  = (const float*)d_in[5];
    const float* fcsn_w1 = (const float*)d_in[6];
    const float* fcsn_b1 = (const float*)d_in[7];
    const float* fcsn_w2 = (const float*)d_in[8];
    const float* fcsn_b2 = (const float*)d_in[9];
    const float* cls_w   = (const float*)d_in[10];
    const float* cls_b   = (const float*)d_in[11];

    float* out = (float*)d_out;
    float* out_ks   = out + OUT_KS;
    float* out_cats = out + OUT_CATS;
    float* out_asp  = out + OUT_ASP;
    float* out_aks  = out + OUT_AKS;

    // k_spatial dynamic smem: 2 feature buffers + w + sv + 2 mbarriers
    const int smem1 = 2 * FEAT_BYTES + (D_LEN + 64) * sizeof(float) + 16;
    cudaFuncSetAttribute(k_spatial, cudaFuncAttributeMaxDynamicSharedMemorySize, smem1);

    k_zero<<<(N_SEG * D_LEN + 255) / 256, 256>>>();
    {
        dim3 g(16, 16, 3), b(32, 8);
        k_wt<<<g, b>>>(fcsn_w1);
    }
    k_spatial<<<152, 512, smem1>>>(feature, seg_ids, att_w, att_b, out_asp);
    {
        dim3 g(N_SEG / 32, D_LEN / 32), b(32, 8);
        k_segmean<<<g, b>>>();
    }
    {
        dim3 g(D_LEN / 32, N_SEG / 32);
        k_conv1<<<g, 256>>>(fcsn_b1);
    }
    k_conv2<<<N_SEG / 8, 256>>>(fcsn_w2, fcsn_b2, out_ks);
    k_fk<<<(N_CLASS + 3) / 4, 512>>>();
    k_final<<<1, 512>>>(att2_w, att2_b, cls_w, cls_b, out_aks, out_cats);
}

// round 3
// speedup vs baseline: 1.2868x; 1.1145x over previous
#include <cuda_runtime.h>
#include <cuda_bf16.h>
#include <cstdint>
#include <math.h>

// ---------------- problem constants ----------------
#define T_LEN   4096
#define R_LEN   49
#define D_LEN   512
#define N_SEG   256
#define N_CLASS 106
#define N_CAT   18

#define FEAT_FLOATS (R_LEN * D_LEN)       // 25088

// output layout: keysteps[106*256], cats[18], alphas_sp[4096*49], alphas_ks[106]
#define OUT_KS   0
#define OUT_CATS (N_CLASS * N_SEG)
#define OUT_ASP  (OUT_CATS + N_CAT)
#define OUT_AKS  (OUT_ASP + T_LEN * R_LEN)

// ---------------- scratch ----------------
__device__ float g_segsum[N_SEG * D_LEN];     // [s][d]
__device__ float g_cnt[N_SEG];
__device__ float g_w1t[3 * D_LEN * D_LEN];    // w1 transposed: [k][i][o]
__device__ float g_h[D_LEN * N_SEG];          // conv1 output (relu): [o][s]
__device__ float g_att[N_CLASS * N_SEG];      // softmax over classes: [m][s]
__device__ float g_fk[N_CLASS * D_LEN];       // f_keysteps: [m][d]

// ---------------- K0: zero segment accumulators ----------------
__global__ void k_zero() {
    int i = blockIdx.x * 256 + threadIdx.x;
    if (i < N_SEG * D_LEN) g_segsum[i] = 0.f;
    if (i < N_SEG) g_cnt[i] = 0.f;
}

// ---------------- K_wt: tiled transpose conv1 weights [O,I,K] -> [K,I,O] ----------------
__global__ void k_wt(const float* __restrict__ w1) {
    __shared__ float tl[32][33];
    int o0 = blockIdx.x * 32, i0 = blockIdx.y * 32, k = blockIdx.z;
    int tx = threadIdx.x, ty = threadIdx.y;
    #pragma unroll
    for (int j = ty; j < 32; j += 8)
        tl[j][tx] = w1[(size_t)(o0 + j) * (D_LEN * 3) + (i0 + tx) * 3 + k];
    __syncthreads();
    #pragma unroll
    for (int j = ty; j < 32; j += 8)
        g_w1t[((size_t)k * D_LEN + i0 + j) * D_LEN + o0 + tx] = tl[tx][j];
}

// ---------------- K1: spatial attention + segment accumulation ----------------
// one block per t, 512 threads, streaming LDG; pass B re-reads tile from L1/L2
__global__ void __launch_bounds__(512)
k_spatial(const float* __restrict__ feature,
          const int* __restrict__ seg_ids,
          const float* __restrict__ att_w,
          const float* __restrict__ att_b,
          float* __restrict__ alphas_out) {
    __shared__ float sv[64];

    const int t = blockIdx.x;
    const int tid = threadIdx.x;
    const int warp = tid >> 5, lane = tid & 31;
    const float* fbase = feature + (size_t)t * FEAT_FLOATS;

    // att_w in registers as float4
    float4 w4[4];
    {
        const float4* wv = (const float4*)att_w;
        #pragma unroll
        for (int j = 0; j < 4; j++) w4[j] = wv[lane + 32 * j];
    }
    const float ab = att_b[0];

    // ---- pass A: per-row dots (each row read once from DRAM, coalesced f4) ----
    for (int r = warp; r < R_LEN; r += 16) {
        const float4* fr = (const float4*)(fbase + r * D_LEN);
        float acc = 0.f;
        #pragma unroll
        for (int j = 0; j < 4; j++) {
            float4 v = fr[lane + 32 * j];
            acc += v.x * w4[j].x + v.y * w4[j].y + v.z * w4[j].z + v.w * w4[j].w;
        }
        #pragma unroll
        for (int o = 16; o; o >>= 1) acc += __shfl_xor_sync(0xffffffffu, acc, o);
        if (!lane) sv[r] = acc + ab;
    }
    __syncthreads();

    // ---- softmax over 49 rows (warp 0) ----
    if (warp == 0) {
        float v0 = (lane < R_LEN) ? sv[lane] : -1e30f;
        float v1 = (lane + 32 < R_LEN) ? sv[lane + 32] : -1e30f;
        float mx = fmaxf(v0, v1);
        #pragma unroll
        for (int o = 16; o; o >>= 1) mx = fmaxf(mx, __shfl_xor_sync(0xffffffffu, mx, o));
        float e0 = (lane < R_LEN) ? __expf(v0 - mx) : 0.f;
        float e1 = (lane + 32 < R_LEN) ? __expf(v1 - mx) : 0.f;
        float sum = e0 + e1;
        #pragma unroll
        for (int o = 16; o; o >>= 1) sum += __shfl_xor_sync(0xffffffffu, sum, o);
        float inv = 1.f / sum;
        if (lane < R_LEN) {
            float a = e0 * inv;
            sv[lane] = a;
            alphas_out[t * R_LEN + lane] = a;
        }
        if (lane + 32 < R_LEN) {
            float a = e1 * inv;
            sv[lane + 32] = a;
            alphas_out[t * R_LEN + lane + 32] = a;
        }
    }
    __syncthreads();

    // ---- pass B: fbar[d] = sum_r f[r][d]*alpha[r] (re-read from L1/L2) ----
    float acc = 0.f;
    #pragma unroll
    for (int r = 0; r < R_LEN; r++) acc += fbase[r * D_LEN + tid] * sv[r];
    const int seg = __ldg(&seg_ids[t]);
    atomicAdd(&g_segsum[seg * D_LEN + tid], acc);
    if (tid == 0) atomicAdd(&g_cnt[seg], 1.f);
}

// ---------------- K3: conv1 (k=3, SAME) as tiled GEMM + relu ----------------
// reads g_segsum[s][d] directly with on-the-fly 1/cnt (segment mean fused)
__global__ void k_conv1(const float* __restrict__ b1) {
    __shared__ float Wt[32][33];   // [ii][oo]
    __shared__ float Xt[32][33];   // [ii][ss]
    __shared__ float icnt[34];     // inv count for s0-1 .. s0+32
    int o0 = blockIdx.x * 32, s0 = blockIdx.y * 32;
    int tid = threadIdx.x;
    int tx = tid & 15, ty = tid >> 4;
    float acc00 = 0.f, acc01 = 0.f, acc10 = 0.f, acc11 = 0.f;

    if (tid < 34) {
        int sc = s0 + tid - 1;
        float c = (sc >= 0 && sc < N_SEG) ? fmaxf(g_cnt[sc], 1.f) : 1.f;
        icnt[tid] = 1.f / c;
    }
    __syncthreads();

    for (int k = 0; k < 3; k++) {
        for (int ic = 0; ic < D_LEN; ic += 32) {
            // Wt: [ii][oo], oo fast-varying -> coalesced
            #pragma unroll
            for (int l = tid; l < 1024; l += 256) {
                int ii = l >> 5, oo = l & 31;
                Wt[ii][oo] = g_w1t[((size_t)k * D_LEN + ic + ii) * D_LEN + o0 + oo];
            }
            // Xt: [ii][ss], ii fast-varying -> coalesced read of g_segsum[sc][ic+ii]
            #pragma unroll
            for (int l = tid; l < 1024; l += 256) {
                int ii = l & 31, ss = l >> 5;
                int sc = s0 + ss + k - 1;
                float v = (sc >= 0 && sc < N_SEG) ? g_segsum[sc * D_LEN + ic + ii] : 0.f;
                Xt[ii][ss] = v * icnt[ss + k];
            }
            __syncthreads();
            #pragma unroll
            for (int ii = 0; ii < 32; ii++) {
                float w0 = Wt[ii][ty], w1v = Wt[ii][ty + 16];
                float x0 = Xt[ii][tx], x1v = Xt[ii][tx + 16];
                acc00 += w0 * x0; acc01 += w0 * x1v;
                acc10 += w1v * x0; acc11 += w1v * x1v;
            }
            __syncthreads();
        }
    }
    float bia0 = b1[o0 + ty], bia1 = b1[o0 + ty + 16];
    g_h[(o0 + ty)      * N_SEG + s0 + tx]      = fmaxf(acc00 + bia0, 0.f);
    g_h[(o0 + ty)      * N_SEG + s0 + tx + 16] = fmaxf(acc01 + bia0, 0.f);
    g_h[(o0 + ty + 16) * N_SEG + s0 + tx]      = fmaxf(acc10 + bia1, 0.f);
    g_h[(o0 + ty + 16) * N_SEG + s0 + tx + 16] = fmaxf(acc11 + bia1, 0.f);
}

// ---------------- K4: conv2 (1x1) + softmax over classes, fused ----------------
__global__ void k_conv2(const float* __restrict__ w2,
                        const float* __restrict__ b2,
                        float* __restrict__ out_ks) {
    __shared__ float hc[D_LEN * 9];      // [i][j], pad 9
    __shared__ float lg[112 * 9];        // logits [m][j], pad 9
    int s0 = blockIdx.x * 8;
    int tid = threadIdx.x;
    int warp = tid >> 5, lane = tid & 31;

    for (int l = tid; l < D_LEN * 8; l += 256) {
        int i = l >> 3, j = l & 7;
        hc[i * 9 + j] = g_h[i * N_SEG + s0 + j];
    }
    __syncthreads();

    for (int m = warp; m < N_CLASS; m += 8) {
        float acc[8] = {0.f, 0.f, 0.f, 0.f, 0.f, 0.f, 0.f, 0.f};
        const float* wm = w2 + m * D_LEN;
        #pragma unroll 4
        for (int i = lane; i < D_LEN; i += 32) {
            float wv = wm[i];
            const float* hp = &hc[i * 9];
            #pragma unroll
            for (int j = 0; j < 8; j++) acc[j] += wv * hp[j];
        }
        #pragma unroll
        for (int j = 0; j < 8; j++) {
            float a = acc[j];
            #pragma unroll
            for (int o = 16; o; o >>= 1) a += __shfl_xor_sync(0xffffffffu, a, o);
            acc[j] = a;
        }
        if (!lane) {
            float bb = b2[m];
            #pragma unroll
            for (int j = 0; j < 8; j++) lg[m * 9 + j] = acc[j] + bb;
        }
    }
    __syncthreads();

    // softmax over m for s = s0 + warp
    {
        int j = warp;
        int s = s0 + j;
        float v[4], mx = -1e30f;
        #pragma unroll
        for (int q = 0; q < 4; q++) {
            int m = lane + 32 * q;
            v[q] = (m < N_CLASS) ? lg[m * 9 + j] : -1e30f;
            mx = fmaxf(mx, v[q]);
        }
        #pragma unroll
        for (int o = 16; o; o >>= 1) mx = fmaxf(mx, __shfl_xor_sync(0xffffffffu, mx, o));
        float e[4], sum = 0.f;
        #pragma unroll
        for (int q = 0; q < 4; q++) {
            int m = lane + 32 * q;
            e[q] = (m < N_CLASS) ? __expf(v[q] - mx) : 0.f;
            sum += e[q];
        }
        #pragma unroll
        for (int o = 16; o; o >>= 1) sum += __shfl_xor_sync(0xffffffffu, sum, o);
        float inv = 1.f / sum;
        #pragma unroll
        for (int q = 0; q < 4; q++) {
            int m = lane + 32 * q;
            if (m < N_CLASS) {
                out_ks[m * N_SEG + s] = v[q];
                g_att[m * N_SEG + s] = e[q] * inv;
            }
        }
    }
}

// ---------------- K5: f_keysteps[m][d] = sum_s x[d][s] * att[m][s] ----------------
// x[d][s] = g_segsum[s][d] / cnt[s]; the 1/cnt is folded into the att tile
__global__ void k_fk() {
    __shared__ float a[4][N_SEG];
    int m0 = blockIdx.x * 4;
    int tid = threadIdx.x;
    for (int l = tid; l < 4 * N_SEG; l += 512) {
        int mm = l >> 8, s = l & 255;
        int m = m0 + mm;
        float inv = 1.f / fmaxf(g_cnt[s], 1.f);
        a[mm][s] = (m < N_CLASS) ? g_att[m * N_SEG + s] * inv : 0.f;
    }
    __syncthreads();
    int d = tid;
    float a0 = 0.f, a1 = 0.f, a2 = 0.f, a3 = 0.f;
    #pragma unroll 8
    for (int s = 0; s < N_SEG; s++) {
        float xv = g_segsum[s * D_LEN + d];   // coalesced over d
        a0 += xv * a[0][s];
        a1 += xv * a[1][s];
        a2 += xv * a[2][s];
        a3 += xv * a[3][s];
    }
    if (m0 + 0 < N_CLASS) g_fk[(m0 + 0) * D_LEN + d] = a0;
    if (m0 + 1 < N_CLASS) g_fk[(m0 + 1) * D_LEN + d] = a1;
    if (m0 + 2 < N_CLASS) g_fk[(m0 + 2) * D_LEN + d] = a2;
    if (m0 + 3 < N_CLASS) g_fk[(m0 + 3) * D_LEN + d] = a3;
}

// ---------------- K6: keystep attention + categories ----------------
__global__ void k_final(const float* __restrict__ att2_w,
                        const float* __restrict__ att2_b,
                        const float* __restrict__ cls_w,
                        const float* __restrict__ cls_b,
                        float* __restrict__ out_aks,
                        float* __restrict__ out_cats) {
    __shared__ float s2[128];
    __shared__ float alpha[128];
    __shared__ float fv[D_LEN];
    int tid = threadIdx.x;
    int warp = tid >> 5, lane = tid & 31;

    for (int m = warp; m < N_CLASS; m += 16) {
        float acc = 0.f;
        const float* fm = g_fk + m * D_LEN;
        #pragma unroll 4
        for (int d = lane; d < D_LEN; d += 32) acc += fm[d] * att2_w[d];
        #pragma unroll
        for (int o = 16; o; o >>= 1) acc += __shfl_xor_sync(0xffffffffu, acc, o);
        if (!lane) s2[m] = acc + att2_b[0];
    }
    __syncthreads();

    if (warp == 0) {
        float v[4], mx = -1e30f;
        #pragma unroll
        for (int q = 0; q < 4; q++) {
            int m = lane + 32 * q;
            v[q] = (m < N_CLASS) ? s2[m] : -1e30f;
            mx = fmaxf(mx, v[q]);
        }
        #pragma unroll
        for (int o = 16; o; o >>= 1) mx = fmaxf(mx, __shfl_xor_sync(0xffffffffu, mx, o));
        float e[4], sum = 0.f;
        #pragma unroll
        for (int q = 0; q < 4; q++) {
            int m = lane + 32 * q;
            e[q] = (m < N_CLASS) ? __expf(v[q] - mx) : 0.f;
            sum += e[q];
        }
        #pragma unroll
        for (int o = 16; o; o >>= 1) sum += __shfl_xor_sync(0xffffffffu, sum, o);
        float inv = 1.f / sum;
        #pragma unroll
        for (int q = 0; q < 4; q++) {
            int m = lane + 32 * q;
            if (m < N_CLASS) {
                float a = e[q] * inv;
                alpha[m] = a;
                out_aks[m] = a;
            }
        }
    }
    __syncthreads();

    {
        int d = tid;
        float acc = 0.f;
        #pragma unroll 8
        for (int m = 0; m < N_CLASS; m++) acc += g_fk[m * D_LEN + d] * alpha[m];
        fv[d] = acc;
    }
    __syncthreads();

    for (int c = warp; c < N_CAT; c += 16) {
        float acc = 0.f;
        #pragma unroll 4
        for (int d = lane; d < D_LEN; d += 32) acc += fv[d] * cls_w[d * N_CAT + c];
        #pragma unroll
        for (int o = 16; o; o >>= 1) acc += __shfl_xor_sync(0xffffffffu, acc, o);
        if (!lane) out_cats[c] = acc + cls_b[c];
    }
}

// ---------------- launch ----------------
extern "C" void kernel_launch(void* const* d_in, const int* in_sizes, int n_in,
                              void* d_out, int out_size) {
    const float* feature = (const float*)d_in[0];
    const int*   seg_ids = (const int*)d_in[1];
    const float* att_w   = (const float*)d_in[2];
    const float* att_b   = (const float*)d_in[3];
    const float* att2_w  = (const float*)d_in[4];
    const float* att2_b  = (const float*)d_in[5];
    const float* fcsn_w1 = (const float*)d_in[6];
    const float* fcsn_b1 = (const float*)d_in[7];
    const float* fcsn_w2 = (const float*)d_in[8];
    const float* fcsn_b2 = (const float*)d_in[9];
    const float* cls_w   = (const float*)d_in[10];
    const float* cls_b   = (const float*)d_in[11];

    float* out = (float*)d_out;
    float* out_ks   = out + OUT_KS;
    float* out_cats = out + OUT_CATS;
    float* out_asp  = out + OUT_ASP;
    float* out_aks  = out + OUT_AKS;

    k_zero<<<(N_SEG * D_LEN + 255) / 256, 256>>>();
    {
        dim3 g(16, 16, 3), b(32, 8);
        k_wt<<<g, b>>>(fcsn_w1);
    }
    k_spatial<<<T_LEN, 512>>>(feature, seg_ids, att_w, att_b, out_asp);
    {
        dim3 g(D_LEN / 32, N_SEG / 32);
        k_conv1<<<g, 256>>>(fcsn_b1);
    }
    k_conv2<<<N_SEG / 8, 256>>>(fcsn_w2, fcsn_b2, out_ks);
    k_fk<<<(N_CLASS + 3) / 4, 512>>>();
    k_final<<<1, 512>>>(att2_w, att2_b, cls_w, cls_b, out_aks, out_cats);
}

// round 4
// speedup vs baseline: 1.5385x; 1.1955x over previous
#include <cuda_runtime.h>
#include <cuda_bf16.h>
#include <cstdint>
#include <math.h>

// ---------------- problem constants ----------------
#define T_LEN   4096
#define R_LEN   49
#define D_LEN   512
#define N_SEG   256
#define N_CLASS 106
#define N_CAT   18

#define FEAT_FLOATS (R_LEN * D_LEN)       // 25088

// output layout: keysteps[106*256], cats[18], alphas_sp[4096*49], alphas_ks[106]
#define OUT_KS   0
#define OUT_CATS (N_CLASS * N_SEG)
#define OUT_ASP  (OUT_CATS + N_CAT)
#define OUT_AKS  (OUT_ASP + T_LEN * R_LEN)

// ---------------- scratch ----------------
__device__ float g_segsum[N_SEG * D_LEN];     // [s][d]
__device__ float g_cnt[N_SEG];
__device__ float g_w1t[3 * D_LEN * D_LEN];    // w1 transposed: [k][i][o]
__device__ float g_hacc[D_LEN * N_SEG];       // conv1 pre-activation accumulator: [o][s]
__device__ float g_att[N_CLASS * N_SEG];      // softmax over classes: [m][s]
__device__ float g_fk[N_CLASS * D_LEN];       // f_keysteps: [m][d]

// ---------------- K0: zero accumulators ----------------
__global__ void k_zero() {
    int i = blockIdx.x * 256 + threadIdx.x;
    if (i < N_SEG * D_LEN) { g_segsum[i] = 0.f; g_hacc[i] = 0.f; }
    if (i < N_SEG) g_cnt[i] = 0.f;
}

// ---------------- K_wt: tiled transpose conv1 weights [O,I,K] -> [K,I,O] ----------------
__global__ void k_wt(const float* __restrict__ w1) {
    __shared__ float tl[32][33];
    int o0 = blockIdx.x * 32, i0 = blockIdx.y * 32, k = blockIdx.z;
    int tx = threadIdx.x, ty = threadIdx.y;
    #pragma unroll
    for (int j = ty; j < 32; j += 8)
        tl[j][tx] = w1[(size_t)(o0 + j) * (D_LEN * 3) + (i0 + tx) * 3 + k];
    __syncthreads();
    #pragma unroll
    for (int j = ty; j < 32; j += 8)
        g_w1t[((size_t)k * D_LEN + i0 + j) * D_LEN + o0 + tx] = tl[tx][j];
}

// ---------------- K1: spatial attention + segment accumulation ----------------
// one block per t, 512 threads; feature column held in registers (read once)
__global__ void __launch_bounds__(512)
k_spatial(const float* __restrict__ feature,
          const int* __restrict__ seg_ids,
          const float* __restrict__ att_w,
          const float* __restrict__ att_b,
          float* __restrict__ alphas_out) {
    __shared__ float part[R_LEN][17];
    __shared__ float sv[64];

    const int t = blockIdx.x;
    const int tid = threadIdx.x;
    const int warp = tid >> 5, lane = tid & 31;
    const float* fbase = feature + (size_t)t * FEAT_FLOATS;

    // load this thread's column across all 49 rows (coalesced, 49-deep MLP)
    float v[R_LEN];
    #pragma unroll
    for (int r = 0; r < R_LEN; r++) v[r] = fbase[r * D_LEN + tid];

    const float wt = att_w[tid];
    const float ab = att_b[0];

    // per-row dot: shuffle-reduce within warp, partials to smem
    #pragma unroll
    for (int r = 0; r < R_LEN; r++) {
        float p = v[r] * wt;
        #pragma unroll
        for (int o = 16; o; o >>= 1) p += __shfl_xor_sync(0xffffffffu, p, o);
        if (!lane) part[r][warp] = p;
    }
    __syncthreads();

    // combine 16 warp partials per row
    if (tid < R_LEN) {
        float s = 0.f;
        #pragma unroll
        for (int j = 0; j < 16; j++) s += part[tid][j];
        sv[tid] = s + ab;
    }
    __syncthreads();

    // softmax over 49 rows (warp 0); sv becomes alphas
    if (warp == 0) {
        float v0 = (lane < R_LEN) ? sv[lane] : -1e30f;
        float v1 = (lane + 32 < R_LEN) ? sv[lane + 32] : -1e30f;
        float mx = fmaxf(v0, v1);
        #pragma unroll
        for (int o = 16; o; o >>= 1) mx = fmaxf(mx, __shfl_xor_sync(0xffffffffu, mx, o));
        float e0 = (lane < R_LEN) ? __expf(v0 - mx) : 0.f;
        float e1 = (lane + 32 < R_LEN) ? __expf(v1 - mx) : 0.f;
        float sum = e0 + e1;
        #pragma unroll
        for (int o = 16; o; o >>= 1) sum += __shfl_xor_sync(0xffffffffu, sum, o);
        float inv = 1.f / sum;
        if (lane < R_LEN) {
            float a = e0 * inv;
            sv[lane] = a;
            alphas_out[t * R_LEN + lane] = a;
        }
        if (lane + 32 < R_LEN) {
            float a = e1 * inv;
            sv[lane + 32] = a;
            alphas_out[t * R_LEN + lane + 32] = a;
        }
    }
    __syncthreads();

    // weighted sum from registers
    float acc = 0.f;
    #pragma unroll
    for (int r = 0; r < R_LEN; r++) acc += v[r] * sv[r];
    const int seg = __ldg(&seg_ids[t]);
    atomicAdd(&g_segsum[seg * D_LEN + tid], acc);
    if (tid == 0) atomicAdd(&g_cnt[seg], 1.f);
}

// ---------------- K3: conv1 as split-K tiled GEMM, partials via atomicAdd ----------------
// grid (16 o-tiles, 8 s-tiles, 6 K-splits): split = (tap k) x (ic half)
// reads g_segsum[s][d] directly with 1/cnt folded (segment mean fused)
__global__ void k_conv1() {
    __shared__ float Wt[32][33];   // [ii][oo]
    __shared__ float Xt[32][33];   // [ii][ss]
    __shared__ float icnt[34];     // inv count for s0-1 .. s0+32
    int o0 = blockIdx.x * 32, s0 = blockIdx.y * 32;
    int kk = blockIdx.z;
    int k = kk >> 1;                 // tap 0..2
    int ich = (kk & 1) * (D_LEN / 2);
    int tid = threadIdx.x;
    int tx = tid & 15, ty = tid >> 4;
    float acc00 = 0.f, acc01 = 0.f, acc10 = 0.f, acc11 = 0.f;

    if (tid < 34) {
        int sc = s0 + tid - 1;
        float c = (sc >= 0 && sc < N_SEG) ? fmaxf(g_cnt[sc], 1.f) : 1.f;
        icnt[tid] = 1.f / c;
    }
    __syncthreads();

    for (int ic = ich; ic < ich + D_LEN / 2; ic += 32) {
        #pragma unroll
        for (int l = tid; l < 1024; l += 256) {
            int ii = l >> 5, oo = l & 31;
            Wt[ii][oo] = g_w1t[((size_t)k * D_LEN + ic + ii) * D_LEN + o0 + oo];
        }
        #pragma unroll
        for (int l = tid; l < 1024; l += 256) {
            int ii = l & 31, ss = l >> 5;
            int sc = s0 + ss + k - 1;
            float v = (sc >= 0 && sc < N_SEG) ? g_segsum[sc * D_LEN + ic + ii] : 0.f;
            Xt[ii][ss] = v * icnt[ss + k];
        }
        __syncthreads();
        #pragma unroll
        for (int ii = 0; ii < 32; ii++) {
            float w0 = Wt[ii][ty], w1v = Wt[ii][ty + 16];
            float x0 = Xt[ii][tx], x1v = Xt[ii][tx + 16];
            acc00 += w0 * x0; acc01 += w0 * x1v;
            acc10 += w1v * x0; acc11 += w1v * x1v;
        }
        __syncthreads();
    }
    atomicAdd(&g_hacc[(o0 + ty)      * N_SEG + s0 + tx],      acc00);
    atomicAdd(&g_hacc[(o0 + ty)      * N_SEG + s0 + tx + 16], acc01);
    atomicAdd(&g_hacc[(o0 + ty + 16) * N_SEG + s0 + tx],      acc10);
    atomicAdd(&g_hacc[(o0 + ty + 16) * N_SEG + s0 + tx + 16], acc11);
}

// ---------------- K4: bias+relu + conv2 (1x1) + softmax over classes, fused ----------------
__global__ void k_conv2(const float* __restrict__ b1,
                        const float* __restrict__ w2,
                        const float* __restrict__ b2,
                        float* __restrict__ out_ks) {
    __shared__ float hc[D_LEN * 9];      // [i][j], pad 9
    __shared__ float lg[112 * 9];        // logits [m][j], pad 9
    int s0 = blockIdx.x * 8;
    int tid = threadIdx.x;
    int warp = tid >> 5, lane = tid & 31;

    for (int l = tid; l < D_LEN * 8; l += 256) {
        int i = l >> 3, j = l & 7;
        hc[i * 9 + j] = fmaxf(g_hacc[i * N_SEG + s0 + j] + b1[i], 0.f);
    }
    __syncthreads();

    for (int m = warp; m < N_CLASS; m += 8) {
        float acc[8] = {0.f, 0.f, 0.f, 0.f, 0.f, 0.f, 0.f, 0.f};
        const float* wm = w2 + m * D_LEN;
        #pragma unroll 4
        for (int i = lane; i < D_LEN; i += 32) {
            float wv = wm[i];
            const float* hp = &hc[i * 9];
            #pragma unroll
            for (int j = 0; j < 8; j++) acc[j] += wv * hp[j];
        }
        #pragma unroll
        for (int j = 0; j < 8; j++) {
            float a = acc[j];
            #pragma unroll
            for (int o = 16; o; o >>= 1) a += __shfl_xor_sync(0xffffffffu, a, o);
            acc[j] = a;
        }
        if (!lane) {
            float bb = b2[m];
            #pragma unroll
            for (int j = 0; j < 8; j++) lg[m * 9 + j] = acc[j] + bb;
        }
    }
    __syncthreads();

    // softmax over m for s = s0 + warp
    {
        int j = warp;
        int s = s0 + j;
        float v[4], mx = -1e30f;
        #pragma unroll
        for (int q = 0; q < 4; q++) {
            int m = lane + 32 * q;
            v[q] = (m < N_CLASS) ? lg[m * 9 + j] : -1e30f;
            mx = fmaxf(mx, v[q]);
        }
        #pragma unroll
        for (int o = 16; o; o >>= 1) mx = fmaxf(mx, __shfl_xor_sync(0xffffffffu, mx, o));
        float e[4], sum = 0.f;
        #pragma unroll
        for (int q = 0; q < 4; q++) {
            int m = lane + 32 * q;
            e[q] = (m < N_CLASS) ? __expf(v[q] - mx) : 0.f;
            sum += e[q];
        }
        #pragma unroll
        for (int o = 16; o; o >>= 1) sum += __shfl_xor_sync(0xffffffffu, sum, o);
        float inv = 1.f / sum;
        #pragma unroll
        for (int q = 0; q < 4; q++) {
            int m = lane + 32 * q;
            if (m < N_CLASS) {
                out_ks[m * N_SEG + s] = v[q];
                g_att[m * N_SEG + s] = e[q] * inv;
            }
        }
    }
}

// ---------------- K5: f_keysteps[m][d] = sum_s x[d][s] * att[m][s] ----------------
__global__ void k_fk() {
    __shared__ float a[4][N_SEG];
    int m0 = blockIdx.x * 4;
    int tid = threadIdx.x;
    for (int l = tid; l < 4 * N_SEG; l += 512) {
        int mm = l >> 8, s = l & 255;
        int m = m0 + mm;
        float inv = 1.f / fmaxf(g_cnt[s], 1.f);
        a[mm][s] = (m < N_CLASS) ? g_att[m * N_SEG + s] * inv : 0.f;
    }
    __syncthreads();
    int d = tid;
    float a0 = 0.f, a1 = 0.f, a2 = 0.f, a3 = 0.f;
    #pragma unroll 8
    for (int s = 0; s < N_SEG; s++) {
        float xv = g_segsum[s * D_LEN + d];   // coalesced over d
        a0 += xv * a[0][s];
        a1 += xv * a[1][s];
        a2 += xv * a[2][s];
        a3 += xv * a[3][s];
    }
    if (m0 + 0 < N_CLASS) g_fk[(m0 + 0) * D_LEN + d] = a0;
    if (m0 + 1 < N_CLASS) g_fk[(m0 + 1) * D_LEN + d] = a1;
    if (m0 + 2 < N_CLASS) g_fk[(m0 + 2) * D_LEN + d] = a2;
    if (m0 + 3 < N_CLASS) g_fk[(m0 + 3) * D_LEN + d] = a3;
}

// ---------------- K6: keystep attention + categories ----------------
__global__ void k_final(const float* __restrict__ att2_w,
                        const float* __restrict__ att2_b,
                        const float* __restrict__ cls_w,
                        const float* __restrict__ cls_b,
                        float* __restrict__ out_aks,
                        float* __restrict__ out_cats) {
    __shared__ float s2[128];
    __shared__ float alpha[128];
    __shared__ float fv[D_LEN];
    int tid = threadIdx.x;
    int warp = tid >> 5, lane = tid & 31;

    for (int m = warp; m < N_CLASS; m += 16) {
        float acc = 0.f;
        const float* fm = g_fk + m * D_LEN;
        #pragma unroll 4
        for (int d = lane; d < D_LEN; d += 32) acc += fm[d] * att2_w[d];
        #pragma unroll
        for (int o = 16; o; o >>= 1) acc += __shfl_xor_sync(0xffffffffu, acc, o);
        if (!lane) s2[m] = acc + att2_b[0];
    }
    __syncthreads();

    if (warp == 0) {
        float v[4], mx = -1e30f;
        #pragma unroll
        for (int q = 0; q < 4; q++) {
            int m = lane + 32 * q;
            v[q] = (m < N_CLASS) ? s2[m] : -1e30f;
            mx = fmaxf(mx, v[q]);
        }
        #pragma unroll
        for (int o = 16; o; o >>= 1) mx = fmaxf(mx, __shfl_xor_sync(0xffffffffu, mx, o));
        float e[4], sum = 0.f;
        #pragma unroll
        for (int q = 0; q < 4; q++) {
            int m = lane + 32 * q;
            e[q] = (m < N_CLASS) ? __expf(v[q] - mx) : 0.f;
            sum += e[q];
        }
        #pragma unroll
        for (int o = 16; o; o >>= 1) sum += __shfl_xor_sync(0xffffffffu, sum, o);
        float inv = 1.f / sum;
        #pragma unroll
        for (int q = 0; q < 4; q++) {
            int m = lane + 32 * q;
            if (m < N_CLASS) {
                float a = e[q] * inv;
                alpha[m] = a;
                out_aks[m] = a;
            }
        }
    }
    __syncthreads();

    {
        int d = tid;
        float acc = 0.f;
        #pragma unroll 8
        for (int m = 0; m < N_CLASS; m++) acc += g_fk[m * D_LEN + d] * alpha[m];
        fv[d] = acc;
    }
    __syncthreads();

    for (int c = warp; c < N_CAT; c += 16) {
        float acc = 0.f;
        #pragma unroll 4
        for (int d = lane; d < D_LEN; d += 32) acc += fv[d] * cls_w[d * N_CAT + c];
        #pragma unroll
        for (int o = 16; o; o >>= 1) acc += __shfl_xor_sync(0xffffffffu, acc, o);
        if (!lane) out_cats[c] = acc + cls_b[c];
    }
}

// ---------------- launch ----------------
extern "C" void kernel_launch(void* const* d_in, const int* in_sizes, int n_in,
                              void* d_out, int out_size) {
    const float* feature = (const float*)d_in[0];
    const int*   seg_ids = (const int*)d_in[1];
    const float* att_w   = (const float*)d_in[2];
    const float* att_b   = (const float*)d_in[3];
    const float* att2_w  = (const float*)d_in[4];
    const float* att2_b  = (const float*)d_in[5];
    const float* fcsn_w1 = (const float*)d_in[6];
    const float* fcsn_b1 = (const float*)d_in[7];
    const float* fcsn_w2 = (const float*)d_in[8];
    const float* fcsn_b2 = (const float*)d_in[9];
    const float* cls_w   = (const float*)d_in[10];
    const float* cls_b   = (const float*)d_in[11];

    float* out = (float*)d_out;
    float* out_ks   = out + OUT_KS;
    float* out_cats = out + OUT_CATS;
    float* out_asp  = out + OUT_ASP;
    float* out_aks  = out + OUT_AKS;

    k_zero<<<(N_SEG * D_LEN + 255) / 256, 256>>>();
    {
        dim3 g(16, 16, 3), b(32, 8);
        k_wt<<<g, b>>>(fcsn_w1);
    }
    k_spatial<<<T_LEN, 512>>>(feature, seg_ids, att_w, att_b, out_asp);
    {
        dim3 g(D_LEN / 32, N_SEG / 32, 6);
        k_conv1<<<g, 256>>>();
    }
    k_conv2<<<N_SEG / 8, 256>>>(fcsn_b1, fcsn_w2, fcsn_b2, out_ks);
    k_fk<<<(N_CLASS + 3) / 4, 512>>>();
    k_final<<<1, 512>>>(att2_w, att2_b, cls_w, cls_b, out_aks, out_cats);
}

// round 5
// speedup vs baseline: 1.9525x; 1.2691x over previous
#include <cuda_runtime.h>
#include <cuda_bf16.h>
#include <cstdint>
#include <math.h>

// ---------------- problem constants ----------------
#define T_LEN   4096
#define R_LEN   49
#define D_LEN   512
#define N_SEG   256
#define N_CLASS 106
#define N_CAT   18

#define FEAT_FLOATS (R_LEN * D_LEN)       // 25088

// output layout: keysteps[106*256], cats[18], alphas_sp[4096*49], alphas_ks[106]
#define OUT_KS   0
#define OUT_CATS (N_CLASS * N_SEG)
#define OUT_ASP  (OUT_CATS + N_CAT)
#define OUT_AKS  (OUT_ASP + T_LEN * R_LEN)

// ---------------- scratch ----------------
__device__ float g_segsum[N_SEG * D_LEN];     // [s][d]
__device__ float g_cnt[N_SEG];
__device__ float g_w1t[3 * D_LEN * D_LEN];    // w1 transposed: [k][i][o]
__device__ float g_hacc[D_LEN * N_SEG];       // conv1 pre-activation accumulator: [o][s]
__device__ float g_att[N_CLASS * N_SEG];      // softmax over classes: [m][s]
__device__ float g_fk[N_CLASS * D_LEN];       // f_keysteps: [m][d]

// ---------------- K0: zero accumulators ----------------
__global__ void k_zero() {
    int i = blockIdx.x * 256 + threadIdx.x;
    if (i < N_SEG * D_LEN) { g_segsum[i] = 0.f; g_hacc[i] = 0.f; }
    if (i < N_SEG) g_cnt[i] = 0.f;
}

// ---------------- K_wt: tiled transpose conv1 weights [O,I,K] -> [K,I,O] ----------------
__global__ void k_wt(const float* __restrict__ w1) {
    __shared__ float tl[32][33];
    int o0 = blockIdx.x * 32, i0 = blockIdx.y * 32, k = blockIdx.z;
    int tx = threadIdx.x, ty = threadIdx.y;
    #pragma unroll
    for (int j = ty; j < 32; j += 8)
        tl[j][tx] = w1[(size_t)(o0 + j) * (D_LEN * 3) + (i0 + tx) * 3 + k];
    __syncthreads();
    #pragma unroll
    for (int j = ty; j < 32; j += 8)
        g_w1t[((size_t)k * D_LEN + i0 + j) * D_LEN + o0 + tx] = tl[tx][j];
}

// ---------------- K1: spatial attention + segment accumulation ----------------
// one block per t, 512 threads; pass A: warp-per-row float4 dots;
// pass B: float4 weighted sum in 4 row-groups, combined in smem.
__global__ void __launch_bounds__(512)
k_spatial(const float* __restrict__ feature,
          const int* __restrict__ seg_ids,
          const float* __restrict__ att_w,
          const float* __restrict__ att_b,
          float* __restrict__ alphas_out) {
    __shared__ float sv[64];
    __shared__ float4 part4[4][128];   // 8KB

    const int t = blockIdx.x;
    const int tid = threadIdx.x;
    const int warp = tid >> 5, lane = tid & 31;
    const float4* f4 = (const float4*)(feature + (size_t)t * FEAT_FLOATS);

    // att_w in registers as float4
    float4 w4[4];
    {
        const float4* wv = (const float4*)att_w;
        #pragma unroll
        for (int j = 0; j < 4; j++) w4[j] = wv[lane + 32 * j];
    }
    const float ab = att_b[0];

    // ---- pass A: per-row dots (coalesced f4, each row once from DRAM) ----
    for (int r = warp; r < R_LEN; r += 16) {
        const float4* fr = f4 + r * 128;
        float acc = 0.f;
        #pragma unroll
        for (int j = 0; j < 4; j++) {
            float4 v = fr[lane + 32 * j];
            acc += v.x * w4[j].x + v.y * w4[j].y + v.z * w4[j].z + v.w * w4[j].w;
        }
        #pragma unroll
        for (int o = 16; o; o >>= 1) acc += __shfl_xor_sync(0xffffffffu, acc, o);
        if (!lane) sv[r] = acc + ab;
    }
    __syncthreads();

    // ---- softmax over 49 rows (warp 0); sv becomes alphas ----
    if (warp == 0) {
        float v0 = (lane < R_LEN) ? sv[lane] : -1e30f;
        float v1 = (lane + 32 < R_LEN) ? sv[lane + 32] : -1e30f;
        float mx = fmaxf(v0, v1);
        #pragma unroll
        for (int o = 16; o; o >>= 1) mx = fmaxf(mx, __shfl_xor_sync(0xffffffffu, mx, o));
        float e0 = (lane < R_LEN) ? __expf(v0 - mx) : 0.f;
        float e1 = (lane + 32 < R_LEN) ? __expf(v1 - mx) : 0.f;
        float sum = e0 + e1;
        #pragma unroll
        for (int o = 16; o; o >>= 1) sum += __shfl_xor_sync(0xffffffffu, sum, o);
        float inv = 1.f / sum;
        if (lane < R_LEN) {
            float a = e0 * inv;
            sv[lane] = a;
            alphas_out[t * R_LEN + lane] = a;
        }
        if (lane + 32 < R_LEN) {
            float a = e1 * inv;
            sv[lane + 32] = a;
            alphas_out[t * R_LEN + lane + 32] = a;
        }
    }
    __syncthreads();

    // ---- pass B: fbar quad q = sum_r alpha[r] * f4[r][q], rows split 4 ways ----
    {
        const int q = tid & 127, g = tid >> 7;
        float4 acc = make_float4(0.f, 0.f, 0.f, 0.f);
        for (int r = g; r < R_LEN; r += 4) {
            float a = sv[r];
            float4 v = f4[r * 128 + q];
            acc.x += v.x * a; acc.y += v.y * a;
            acc.z += v.z * a; acc.w += v.w * a;
        }
        part4[g][q] = acc;
    }
    __syncthreads();

    if (tid < 128) {
        float4 s0 = part4[0][tid], s1 = part4[1][tid];
        float4 s2 = part4[2][tid], s3 = part4[3][tid];
        float4 s;
        s.x = (s0.x + s1.x) + (s2.x + s3.x);
        s.y = (s0.y + s1.y) + (s2.y + s3.y);
        s.z = (s0.z + s1.z) + (s2.z + s3.z);
        s.w = (s0.w + s1.w) + (s2.w + s3.w);
        const int seg = __ldg(&seg_ids[t]);
        float* dst = &g_segsum[seg * D_LEN + tid * 4];
        atomicAdd(dst + 0, s.x);
        atomicAdd(dst + 1, s.y);
        atomicAdd(dst + 2, s.z);
        atomicAdd(dst + 3, s.w);
        if (tid == 0) atomicAdd(&g_cnt[seg], 1.f);
    }
}

// ---------------- K3: conv1 as split-K tiled GEMM (64x64 tiles, 4x4/thread) ----------------
// grid (8 o-tiles, 4 s-tiles, 6 K-splits); split = (tap k) x (ic half)
#define CW 68   // padded smem row stride (floats), 272B keeps 16B alignment
__global__ void k_conv1() {
    __shared__ float Wt[32 * CW];   // [ii][oo] 32x64
    __shared__ float Xt[32 * CW];   // [ii][ss] 32x64
    __shared__ float icnt[66];      // inv count for s0-1 .. s0+64
    int o0 = blockIdx.x * 64, s0 = blockIdx.y * 64;
    int kk = blockIdx.z;
    int k = kk >> 1;                 // tap 0..2
    int ich = (kk & 1) * (D_LEN / 2);
    int tid = threadIdx.x;
    int tx = tid & 15, ty = tid >> 4;
    float acc[4][4];
    #pragma unroll
    for (int a = 0; a < 4; a++)
        #pragma unroll
        for (int b = 0; b < 4; b++) acc[a][b] = 0.f;

    if (tid < 66) {
        int sc = s0 + tid - 1;
        float c = (sc >= 0 && sc < N_SEG) ? fmaxf(g_cnt[sc], 1.f) : 1.f;
        icnt[tid] = 1.f / c;
    }
    __syncthreads();

    for (int ic = ich; ic < ich + D_LEN / 2; ic += 32) {
        #pragma unroll
        for (int l = tid; l < 2048; l += 256) {
            int ii = l >> 6, oo = l & 63;
            Wt[ii * CW + oo] = g_w1t[((size_t)k * D_LEN + ic + ii) * D_LEN + o0 + oo];
        }
        #pragma unroll
        for (int l = tid; l < 2048; l += 256) {
            int ii = l & 31, ss = l >> 5;
            int sc = s0 + ss + k - 1;
            float v = (sc >= 0 && sc < N_SEG) ? g_segsum[sc * D_LEN + ic + ii] : 0.f;
            Xt[ii * CW + ss] = v * icnt[ss + k];
        }
        __syncthreads();
        #pragma unroll
        for (int ii = 0; ii < 32; ii++) {
            float4 wv = *(const float4*)&Wt[ii * CW + ty * 4];
            float4 xv = *(const float4*)&Xt[ii * CW + tx * 4];
            acc[0][0] += wv.x * xv.x; acc[0][1] += wv.x * xv.y;
            acc[0][2] += wv.x * xv.z; acc[0][3] += wv.x * xv.w;
            acc[1][0] += wv.y * xv.x; acc[1][1] += wv.y * xv.y;
            acc[1][2] += wv.y * xv.z; acc[1][3] += wv.y * xv.w;
            acc[2][0] += wv.z * xv.x; acc[2][1] += wv.z * xv.y;
            acc[2][2] += wv.z * xv.z; acc[2][3] += wv.z * xv.w;
            acc[3][0] += wv.w * xv.x; acc[3][1] += wv.w * xv.y;
            acc[3][2] += wv.w * xv.z; acc[3][3] += wv.w * xv.w;
        }
        __syncthreads();
    }
    #pragma unroll
    for (int a = 0; a < 4; a++) {
        float* dst = &g_hacc[(o0 + ty * 4 + a) * N_SEG + s0 + tx * 4];
        #pragma unroll
        for (int b = 0; b < 4; b++) atomicAdd(dst + b, acc[a][b]);
    }
}

// ---------------- K4: bias+relu + conv2 (1x1) + softmax over classes, fused ----------------
__global__ void k_conv2(const float* __restrict__ b1,
                        const float* __restrict__ w2,
                        const float* __restrict__ b2,
                        float* __restrict__ out_ks) {
    __shared__ float hc[D_LEN * 9];      // [i][j], pad 9
    __shared__ float lg[112 * 9];        // logits [m][j], pad 9
    int s0 = blockIdx.x * 8;
    int tid = threadIdx.x;
    int warp = tid >> 5, lane = tid & 31;

    for (int l = tid; l < D_LEN * 8; l += 256) {
        int i = l >> 3, j = l & 7;
        hc[i * 9 + j] = fmaxf(g_hacc[i * N_SEG + s0 + j] + b1[i], 0.f);
    }
    __syncthreads();

    for (int m = warp; m < N_CLASS; m += 8) {
        float acc[8] = {0.f, 0.f, 0.f, 0.f, 0.f, 0.f, 0.f, 0.f};
        const float* wm = w2 + m * D_LEN;
        #pragma unroll 4
        for (int i = lane; i < D_LEN; i += 32) {
            float wv = wm[i];
            const float* hp = &hc[i * 9];
            #pragma unroll
            for (int j = 0; j < 8; j++) acc[j] += wv * hp[j];
        }
        #pragma unroll
        for (int j = 0; j < 8; j++) {
            float a = acc[j];
            #pragma unroll
            for (int o = 16; o; o >>= 1) a += __shfl_xor_sync(0xffffffffu, a, o);
            acc[j] = a;
        }
        if (!lane) {
            float bb = b2[m];
            #pragma unroll
            for (int j = 0; j < 8; j++) lg[m * 9 + j] = acc[j] + bb;
        }
    }
    __syncthreads();

    // softmax over m for s = s0 + warp
    {
        int j = warp;
        int s = s0 + j;
        float v[4], mx = -1e30f;
        #pragma unroll
        for (int q = 0; q < 4; q++) {
            int m = lane + 32 * q;
            v[q] = (m < N_CLASS) ? lg[m * 9 + j] : -1e30f;
            mx = fmaxf(mx, v[q]);
        }
        #pragma unroll
        for (int o = 16; o; o >>= 1) mx = fmaxf(mx, __shfl_xor_sync(0xffffffffu, mx, o));
        float e[4], sum = 0.f;
        #pragma unroll
        for (int q = 0; q < 4; q++) {
            int m = lane + 32 * q;
            e[q] = (m < N_CLASS) ? __expf(v[q] - mx) : 0.f;
            sum += e[q];
        }
        #pragma unroll
        for (int o = 16; o; o >>= 1) sum += __shfl_xor_sync(0xffffffffu, sum, o);
        float inv = 1.f / sum;
        #pragma unroll
        for (int q = 0; q < 4; q++) {
            int m = lane + 32 * q;
            if (m < N_CLASS) {
                out_ks[m * N_SEG + s] = v[q];
                g_att[m * N_SEG + s] = e[q] * inv;
            }
        }
    }
}

// ---------------- K5: f_keysteps[m][d] = sum_s x[d][s] * att[m][s] ----------------
__global__ void k_fk() {
    __shared__ float a[4][N_SEG];
    int m0 = blockIdx.x * 4;
    int tid = threadIdx.x;
    for (int l = tid; l < 4 * N_SEG; l += 512) {
        int mm = l >> 8, s = l & 255;
        int m = m0 + mm;
        float inv = 1.f / fmaxf(g_cnt[s], 1.f);
        a[mm][s] = (m < N_CLASS) ? g_att[m * N_SEG + s] * inv : 0.f;
    }
    __syncthreads();
    int d = tid;
    float a0 = 0.f, a1 = 0.f, a2 = 0.f, a3 = 0.f;
    #pragma unroll 8
    for (int s = 0; s < N_SEG; s++) {
        float xv = g_segsum[s * D_LEN + d];   // coalesced over d
        a0 += xv * a[0][s];
        a1 += xv * a[1][s];
        a2 += xv * a[2][s];
        a3 += xv * a[3][s];
    }
    if (m0 + 0 < N_CLASS) g_fk[(m0 + 0) * D_LEN + d] = a0;
    if (m0 + 1 < N_CLASS) g_fk[(m0 + 1) * D_LEN + d] = a1;
    if (m0 + 2 < N_CLASS) g_fk[(m0 + 2) * D_LEN + d] = a2;
    if (m0 + 3 < N_CLASS) g_fk[(m0 + 3) * D_LEN + d] = a3;
}

// ---------------- K6: keystep attention + categories ----------------
__global__ void k_final(const float* __restrict__ att2_w,
                        const float* __restrict__ att2_b,
                        const float* __restrict__ cls_w,
                        const float* __restrict__ cls_b,
                        float* __restrict__ out_aks,
                        float* __restrict__ out_cats) {
    __shared__ float s2[128];
    __shared__ float alpha[128];
    __shared__ float fv[D_LEN];
    int tid = threadIdx.x;
    int warp = tid >> 5, lane = tid & 31;

    for (int m = warp; m < N_CLASS; m += 16) {
        float acc = 0.f;
        const float* fm = g_fk + m * D_LEN;
        #pragma unroll 4
        for (int d = lane; d < D_LEN; d += 32) acc += fm[d] * att2_w[d];
        #pragma unroll
        for (int o = 16; o; o >>= 1) acc += __shfl_xor_sync(0xffffffffu, acc, o);
        if (!lane) s2[m] = acc + att2_b[0];
    }
    __syncthreads();

    if (warp == 0) {
        float v[4], mx = -1e30f;
        #pragma unroll
        for (int q = 0; q < 4; q++) {
            int m = lane + 32 * q;
            v[q] = (m < N_CLASS) ? s2[m] : -1e30f;
            mx = fmaxf(mx, v[q]);
        }
        #pragma unroll
        for (int o = 16; o; o >>= 1) mx = fmaxf(mx, __shfl_xor_sync(0xffffffffu, mx, o));
        float e[4], sum = 0.f;
        #pragma unroll
        for (int q = 0; q < 4; q++) {
            int m = lane + 32 * q;
            e[q] = (m < N_CLASS) ? __expf(v[q] - mx) : 0.f;
            sum += e[q];
        }
        #pragma unroll
        for (int o = 16; o; o >>= 1) sum += __shfl_xor_sync(0xffffffffu, sum, o);
        float inv = 1.f / sum;
        #pragma unroll
        for (int q = 0; q < 4; q++) {
            int m = lane + 32 * q;
            if (m < N_CLASS) {
                float a = e[q] * inv;
                alpha[m] = a;
                out_aks[m] = a;
            }
        }
    }
    __syncthreads();

    {
        int d = tid;
        float acc = 0.f;
        #pragma unroll 8
        for (int m = 0; m < N_CLASS; m++) acc += g_fk[m * D_LEN + d] * alpha[m];
        fv[d] = acc;
    }
    __syncthreads();

    for (int c = warp; c < N_CAT; c += 16) {
        float acc = 0.f;
        #pragma unroll 4
        for (int d = lane; d < D_LEN; d += 32) acc += fv[d] * cls_w[d * N_CAT + c];
        #pragma unroll
        for (int o = 16; o; o >>= 1) acc += __shfl_xor_sync(0xffffffffu, acc, o);
        if (!lane) out_cats[c] = acc + cls_b[c];
    }
}

// ---------------- launch ----------------
extern "C" void kernel_launch(void* const* d_in, const int* in_sizes, int n_in,
                              void* d_out, int out_size) {
    const float* feature = (const float*)d_in[0];
    const int*   seg_ids = (const int*)d_in[1];
    const float* att_w   = (const float*)d_in[2];
    const float* att_b   = (const float*)d_in[3];
    const float* att2_w  = (const float*)d_in[4];
    const float* att2_b  = (const float*)d_in[5];
    const float* fcsn_w1 = (const float*)d_in[6];
    const float* fcsn_b1 = (const float*)d_in[7];
    const float* fcsn_w2 = (const float*)d_in[8];
    const float* fcsn_b2 = (const float*)d_in[9];
    const float* cls_w   = (const float*)d_in[10];
    const float* cls_b   = (const float*)d_in[11];

    float* out = (float*)d_out;
    float* out_ks   = out + OUT_KS;
    float* out_cats = out + OUT_CATS;
    float* out_asp  = out + OUT_ASP;
    float* out_aks  = out + OUT_AKS;

    k_zero<<<(N_SEG * D_LEN + 255) / 256, 256>>>();
    {
        dim3 g(16, 16, 3), b(32, 8);
        k_wt<<<g, b>>>(fcsn_w1);
    }
    k_spatial<<<T_LEN, 512>>>(feature, seg_ids, att_w, att_b, out_asp);
    {
        dim3 g(D_LEN / 64, N_SEG / 64, 6);
        k_conv1<<<g, 256>>>();
    }
    k_conv2<<<N_SEG / 8, 256>>>(fcsn_b1, fcsn_w2, fcsn_b2, out_ks);
    k_fk<<<(N_CLASS + 3) / 4, 512>>>();
    k_final<<<1, 512>>>(att2_w, att2_b, cls_w, cls_b, out_aks, out_cats);
}